// round 9
// baseline (speedup 1.0000x reference)
#include <cuda_runtime.h>
#include <cstdint>

#define Bb 64
#define Tt 1024
#define Ii 64
#define Hh 512
#define G3 1536
#define MM (Bb*Tt)      // 65536 rows

// ---------------- scratch (device globals: allocation-free) ----------------
__device__ float g_xg[(size_t)MM * G3];   // input-side gates (~403 MB)
__device__ float g_y [(size_t)MM * Hh];   // layer output / hidden history (~134 MB)

struct __align__(128) PadFlag { unsigned v; unsigned pad[31]; };
__device__ PadFlag g_flag[4][32];         // per (group, hidden-block) monotonic step flags

// ---------------- helpers ----------------
__device__ __forceinline__ float to_tf32(float x) {
    unsigned u;
    asm("cvt.rna.tf32.f32 %0, %1;" : "=r"(u) : "f"(x));
    return __uint_as_float(u);
}

__device__ __forceinline__ void mma_tf32(float* c, const unsigned* a, unsigned b0, unsigned b1) {
    asm("mma.sync.aligned.m16n8k8.row.col.f32.tf32.tf32.f32 "
        "{%0,%1,%2,%3},{%4,%5,%6,%7},{%8,%9},{%0,%1,%2,%3};"
        : "+f"(c[0]), "+f"(c[1]), "+f"(c[2]), "+f"(c[3])
        : "r"(a[0]), "r"(a[1]), "r"(a[2]), "r"(a[3]), "r"(b0), "r"(b1));
}

__device__ __forceinline__ unsigned smem_u32(const void* p) {
    return (unsigned)__cvta_generic_to_shared(p);
}

// ---------------- generic tf32 GEMM: C[m][n] = sum_k A[m][k]*W[n][k] + bias[n] ----
// BM=128, BN=64, BK=16, 256 threads, 8 warps as 4x2 (each warp 32x32).
__global__ __launch_bounds__(256) void gemm_tf32(
    const float* __restrict__ A, const float* __restrict__ W,
    const float* __restrict__ bias, float* __restrict__ C,
    int M, int N, int K)
{
    __shared__ float As[128][20];
    __shared__ float Ws[64][20];
    const int tid  = threadIdx.x;
    const int warp = tid >> 5, lane = tid & 31;
    const int gID  = lane >> 2, tig = lane & 3;
    const int wm   = warp >> 1, wn = warp & 1;
    const int m0   = blockIdx.y * 128, n0 = blockIdx.x * 64;

    float acc[2][4][4];
    #pragma unroll
    for (int i = 0; i < 2; i++)
        #pragma unroll
        for (int j = 0; j < 4; j++)
            #pragma unroll
            for (int q = 0; q < 4; q++) acc[i][j][q] = 0.f;

    for (int k0 = 0; k0 < K; k0 += 16) {
        #pragma unroll
        for (int i = 0; i < 2; i++) {
            int idx = tid + i * 256;               // 0..511 float4s
            int r = idx >> 2, cb = idx & 3;
            float4 v = *(const float4*)(A + (size_t)(m0 + r) * K + k0 + cb * 4);
            *(float4*)(&As[r][cb * 4]) =
                make_float4(to_tf32(v.x), to_tf32(v.y), to_tf32(v.z), to_tf32(v.w));
        }
        {
            int r = tid >> 2, cb = tid & 3;        // 256 float4s
            float4 v = *(const float4*)(W + (size_t)(n0 + r) * K + k0 + cb * 4);
            *(float4*)(&Ws[r][cb * 4]) =
                make_float4(to_tf32(v.x), to_tf32(v.y), to_tf32(v.z), to_tf32(v.w));
        }
        __syncthreads();
        #pragma unroll
        for (int s = 0; s < 2; s++) {
            const int kk = s * 8;
            unsigned a[2][4];
            #pragma unroll
            for (int mt = 0; mt < 2; mt++) {
                int r = wm * 32 + mt * 16 + gID;
                a[mt][0] = __float_as_uint(As[r][kk + tig]);
                a[mt][1] = __float_as_uint(As[r + 8][kk + tig]);
                a[mt][2] = __float_as_uint(As[r][kk + tig + 4]);
                a[mt][3] = __float_as_uint(As[r + 8][kk + tig + 4]);
            }
            #pragma unroll
            for (int nt = 0; nt < 4; nt++) {
                int n = wn * 32 + nt * 8 + gID;
                unsigned b0 = __float_as_uint(Ws[n][kk + tig]);
                unsigned b1 = __float_as_uint(Ws[n][kk + tig + 4]);
                #pragma unroll
                for (int mt = 0; mt < 2; mt++)
                    mma_tf32(acc[mt][nt], a[mt], b0, b1);
            }
        }
        __syncthreads();
    }
    #pragma unroll
    for (int mt = 0; mt < 2; mt++) {
        int r0 = m0 + wm * 32 + mt * 16 + gID;
        #pragma unroll
        for (int nt = 0; nt < 4; nt++) {
            int c = n0 + wn * 32 + nt * 8 + tig * 2;
            float bc0 = bias[c], bc1 = bias[c + 1];
            C[(size_t)r0 * N + c]           = acc[mt][nt][0] + bc0;
            C[(size_t)r0 * N + c + 1]       = acc[mt][nt][1] + bc1;
            C[(size_t)(r0 + 8) * N + c]     = acc[mt][nt][2] + bc0;
            C[(size_t)(r0 + 8) * N + c + 1] = acc[mt][nt][3] + bc1;
        }
    }
}

// ---------------- persistent recurrent kernel ----------------
// 128 blocks: bid&3 = batch group (16 batches), bid>>2 = hidden block (16 units).
// W_hh slice (48x512) lives in REGISTERS (96 regs/thread) for all 1024 steps.
#define RP 516          // padded h row stride (floats)
#define PS 49           // padded partial row stride (floats)

__global__ __launch_bounds__(256, 1) void gru_rec(
    const float* __restrict__ xg, const float* __restrict__ whh,
    const float* __restrict__ bhh, float* __restrict__ y)
{
    extern __shared__ float sm[];
    float* h_s  = sm;                     // 16*516
    float* part = h_s + 16 * RP;          // 8*16*49
    float* b_s  = part + 8 * 16 * PS;     // 48
    __shared__ unsigned s_base;

    const int bid  = blockIdx.x;
    const int grp  = bid & 3;
    const int hb   = bid >> 2;
    const int tid  = threadIdx.x;
    const int warp = tid >> 5, lane = tid & 31;
    const int gID  = lane >> 2, tig = lane & 3;
    const int bb   = tid >> 4, uu = tid & 15;
    const int bglob = grp * 16;
    const int k0w  = warp * 64;

    // One-time: load this thread's W_hh fragments into registers (tf32-rounded).
    unsigned breg[8][6][2];
    #pragma unroll
    for (int nt = 0; nt < 6; nt++) {
        int r = nt * 8 + gID;                        // 0..47
        int grow = (r >> 4) * Hh + hb * 16 + (r & 15);
        const float* wrow = whh + (size_t)grow * Hh;
        #pragma unroll
        for (int ks = 0; ks < 8; ks++) {
            int k = k0w + ks * 8 + tig;
            breg[ks][nt][0] = __float_as_uint(to_tf32(wrow[k]));
            breg[ks][nt][1] = __float_as_uint(to_tf32(wrow[k + 4]));
        }
    }
    if (tid < 48) b_s[tid] = bhh[(tid >> 4) * Hh + hb * 16 + (tid & 15)];
    for (int i = tid; i < 16 * RP; i += 256) h_s[i] = 0.f;   // h_0 = 0

    if (tid == 0) s_base = *(volatile unsigned*)&g_flag[grp][hb].v;  // equal across blocks
    __syncthreads();
    const unsigned base = s_base;

    const int b  = bglob + bb;
    const int ug = hb * 16 + uu;

    for (int t = 0; t < Tt; t++) {
        // prefetch input-side gates early (consumed after the reduction)
        const size_t xb = ((size_t)b * Tt + t) * (size_t)G3;
        float xr = __ldg(xg + xb + ug);
        float xz = __ldg(xg + xb + Hh + ug);
        float xn = __ldg(xg + xb + 2 * Hh + ug);

        if (t > 0) {
            // h_{t-1} (already tf32-valued in y): 2048 16B cp.async, 8 per thread
            #pragma unroll
            for (int i = 0; i < 8; i++) {
                int idx = tid + i * 256;
                int r = idx >> 7, cb = idx & 127;
                const float* src = y + ((size_t)(bglob + r) * Tt + (t - 1)) * Hh + cb * 4;
                unsigned dst = smem_u32(h_s + r * RP + cb * 4);
                asm volatile("cp.async.cg.shared.global [%0], [%1], 16;"
                             :: "r"(dst), "l"(src) : "memory");
            }
            asm volatile("cp.async.commit_group;\n\tcp.async.wait_group 0;" ::: "memory");
        }
        __syncthreads();

        // hg partial = h[16 x 64] * Whh^T (this warp's k-slice), B from registers
        float acc[6][4];
        #pragma unroll
        for (int nt = 0; nt < 6; nt++) { acc[nt][0]=acc[nt][1]=acc[nt][2]=acc[nt][3]=0.f; }
        #pragma unroll
        for (int ks = 0; ks < 8; ks++) {
            int k = k0w + ks * 8;
            unsigned a[4];
            a[0] = __float_as_uint(h_s[gID * RP + k + tig]);
            a[1] = __float_as_uint(h_s[(gID + 8) * RP + k + tig]);
            a[2] = __float_as_uint(h_s[gID * RP + k + tig + 4]);
            a[3] = __float_as_uint(h_s[(gID + 8) * RP + k + tig + 4]);
            #pragma unroll
            for (int nt = 0; nt < 6; nt++)
                mma_tf32(acc[nt], a, breg[ks][nt][0], breg[ks][nt][1]);
        }
        float* pw = part + warp * 16 * PS;
        #pragma unroll
        for (int nt = 0; nt < 6; nt++) {
            int c = nt * 8 + tig * 2;
            pw[gID * PS + c]           = acc[nt][0];
            pw[gID * PS + c + 1]       = acc[nt][1];
            pw[(gID + 8) * PS + c]     = acc[nt][2];
            pw[(gID + 8) * PS + c + 1] = acc[nt][3];
        }
        __syncthreads();

        // 8-way k-reduction folded into gate math; one (batch, unit) per thread
        float hr = b_s[uu], hz = b_s[16 + uu], hn = b_s[32 + uu];
        #pragma unroll
        for (int w = 0; w < 8; w++) {
            const float* p = part + w * 16 * PS + bb * PS;
            hr += p[uu]; hz += p[16 + uu]; hn += p[32 + uu];
        }
        float r = 1.f / (1.f + __expf(-(xr + hr)));
        float z = 1.f / (1.f + __expf(-(xz + hz)));
        float n = tanhf(xn + r * hn);
        float hp = h_s[bb * RP + ug];               // h_{t-1} (tf32)
        float hnew = (1.f - z) * n + z * hp;
        y[((size_t)b * Tt + t) * Hh + ug] = to_tf32(hnew);   // store pre-rounded

        // 32-block barrier within batch group: per-block monotonic flags,
        // 32 threads poll one flag each (no atomic serialization, no leader hop)
        __syncthreads();                            // all h_s reads + y stores ordered
        if (t < Tt - 1) {
            if (tid == 0) {
                __threadfence();
                *(volatile unsigned*)&g_flag[grp][hb].v = base + (unsigned)t + 1u;
            }
            if (tid < 32) {
                unsigned tgt = base + (unsigned)t + 1u;
                while ((int)(*(volatile unsigned*)&g_flag[grp][tid].v - tgt) < 0) { }
                __threadfence();
            }
            __syncthreads();
        }
    }
}

// ---------------- launch ----------------
extern "C" void kernel_launch(void* const* d_in, const int* in_sizes, int n_in,
                              void* d_out, int out_size)
{
    const float* x    = (const float*)d_in[0];
    const float* wih0 = (const float*)d_in[1];
    const float* whh0 = (const float*)d_in[2];
    const float* bih0 = (const float*)d_in[3];
    const float* bhh0 = (const float*)d_in[4];
    const float* wih1 = (const float*)d_in[5];
    const float* whh1 = (const float*)d_in[6];
    const float* bih1 = (const float*)d_in[7];
    const float* bhh1 = (const float*)d_in[8];
    const float* fcw  = (const float*)d_in[9];
    const float* fcb  = (const float*)d_in[10];
    float* out = (float*)d_out;

    float *xgp = 0, *yp = 0;
    cudaGetSymbolAddress((void**)&xgp, g_xg);
    cudaGetSymbolAddress((void**)&yp,  g_y);

    const size_t rec_smem = (size_t)(16 * RP + 8 * 16 * PS + 48) * sizeof(float); // 58,304 B
    cudaFuncSetAttribute(gru_rec, cudaFuncAttributeMaxDynamicSharedMemorySize, (int)rec_smem);

    // layer 0: xg0 = x @ w_ih0^T + b_ih0   (K=64)
    gemm_tf32<<<dim3(G3 / 64, MM / 128), 256>>>(x, wih0, bih0, xgp, MM, G3, Ii);
    // layer 0 recurrence -> y
    gru_rec<<<128, 256, rec_smem>>>(xgp, whh0, bhh0, yp);
    // layer 1: xg1 = y0 @ w_ih1^T + b_ih1  (K=512)
    gemm_tf32<<<dim3(G3 / 64, MM / 128), 256>>>(yp, wih1, bih1, xgp, MM, G3, Hh);
    // layer 1 recurrence -> y (y0 dead after xg1)
    gru_rec<<<128, 256, rec_smem>>>(xgp, whh1, bhh1, yp);
    // FC: out = y1 @ fc_w^T + fc_b (N=64)
    gemm_tf32<<<dim3(Ii / 64, MM / 128), 256>>>(yp, fcw, fcb, out, MM, Ii, Hh);
}

// round 10
// speedup vs baseline: 1.5703x; 1.5703x over previous
#include <cuda_runtime.h>
#include <cstdint>

#define Bb 64
#define Tt 1024
#define Ii 64
#define Hh 512
#define G3 1536
#define MM (Bb*Tt)      // 65536 rows

// ---------------- scratch (device globals: allocation-free) ----------------
__device__ float g_xg[(size_t)MM * G3];   // input-side gates, TIME-MAJOR rows (t*B+b)
__device__ float g_y [(size_t)MM * Hh];   // hidden history, TIME-MAJOR rows (t*B+b)

struct __align__(128) PadFlag { unsigned v; unsigned pad[31]; };
__device__ PadFlag g_flag[4][32];         // per (group, producer-block) monotonic step flags

// ---------------- helpers ----------------
__device__ __forceinline__ float to_tf32(float x) {
    unsigned u;
    asm("cvt.rna.tf32.f32 %0, %1;" : "=r"(u) : "f"(x));
    return __uint_as_float(u);
}

__device__ __forceinline__ void mma_tf32(float* c, const unsigned* a, unsigned b0, unsigned b1) {
    asm("mma.sync.aligned.m16n8k8.row.col.f32.tf32.tf32.f32 "
        "{%0,%1,%2,%3},{%4,%5,%6,%7},{%8,%9},{%0,%1,%2,%3};"
        : "+f"(c[0]), "+f"(c[1]), "+f"(c[2]), "+f"(c[3])
        : "r"(a[0]), "r"(a[1]), "r"(a[2]), "r"(a[3]), "r"(b0), "r"(b1));
}

__device__ __forceinline__ unsigned smem_u32(const void* p) {
    return (unsigned)__cvta_generic_to_shared(p);
}

__device__ __forceinline__ void waitflag(const unsigned* p, unsigned tgt) {
    unsigned v;
    asm volatile("ld.global.acquire.gpu.b32 %0, [%1];" : "=r"(v) : "l"(p));
    while ((int)(v - tgt) < 0) {
        __nanosleep(20);
        asm volatile("ld.global.acquire.gpu.b32 %0, [%1];" : "=r"(v) : "l"(p));
    }
}

// ---------------- generic tf32 GEMM: C[m][n] = sum_k A[m][k]*W[n][k] + bias[n] ----
// mode: output row remap. 0: ro=m  1: m=(b*T+t) -> ro=t*B+b   2: m=(t*B+b) -> ro=b*T+t
__global__ __launch_bounds__(256) void gemm_tf32(
    const float* __restrict__ A, const float* __restrict__ W,
    const float* __restrict__ bias, float* __restrict__ C,
    int M, int N, int K, int mode)
{
    __shared__ float As[128][20];
    __shared__ float Ws[64][20];
    const int tid  = threadIdx.x;
    const int warp = tid >> 5, lane = tid & 31;
    const int gID  = lane >> 2, tig = lane & 3;
    const int wm   = warp >> 1, wn = warp & 1;
    const int m0   = blockIdx.y * 128, n0 = blockIdx.x * 64;

    float acc[2][4][4];
    #pragma unroll
    for (int i = 0; i < 2; i++)
        #pragma unroll
        for (int j = 0; j < 4; j++)
            #pragma unroll
            for (int q = 0; q < 4; q++) acc[i][j][q] = 0.f;

    for (int k0 = 0; k0 < K; k0 += 16) {
        #pragma unroll
        for (int i = 0; i < 2; i++) {
            int idx = tid + i * 256;
            int r = idx >> 2, cb = idx & 3;
            float4 v = *(const float4*)(A + (size_t)(m0 + r) * K + k0 + cb * 4);
            *(float4*)(&As[r][cb * 4]) =
                make_float4(to_tf32(v.x), to_tf32(v.y), to_tf32(v.z), to_tf32(v.w));
        }
        {
            int r = tid >> 2, cb = tid & 3;
            float4 v = *(const float4*)(W + (size_t)(n0 + r) * K + k0 + cb * 4);
            *(float4*)(&Ws[r][cb * 4]) =
                make_float4(to_tf32(v.x), to_tf32(v.y), to_tf32(v.z), to_tf32(v.w));
        }
        __syncthreads();
        #pragma unroll
        for (int s = 0; s < 2; s++) {
            const int kk = s * 8;
            unsigned a[2][4];
            #pragma unroll
            for (int mt = 0; mt < 2; mt++) {
                int r = wm * 32 + mt * 16 + gID;
                a[mt][0] = __float_as_uint(As[r][kk + tig]);
                a[mt][1] = __float_as_uint(As[r + 8][kk + tig]);
                a[mt][2] = __float_as_uint(As[r][kk + tig + 4]);
                a[mt][3] = __float_as_uint(As[r + 8][kk + tig + 4]);
            }
            #pragma unroll
            for (int nt = 0; nt < 4; nt++) {
                int n = wn * 32 + nt * 8 + gID;
                unsigned b0 = __float_as_uint(Ws[n][kk + tig]);
                unsigned b1 = __float_as_uint(Ws[n][kk + tig + 4]);
                #pragma unroll
                for (int mt = 0; mt < 2; mt++)
                    mma_tf32(acc[mt][nt], a[mt], b0, b1);
            }
        }
        __syncthreads();
    }
    #pragma unroll
    for (int mt = 0; mt < 2; mt++) {
        #pragma unroll
        for (int rr = 0; rr < 2; rr++) {
            int r = m0 + wm * 32 + mt * 16 + rr * 8 + gID;
            int ro = (mode == 0) ? r
                   : (mode == 1) ? ((r & (Tt - 1)) * Bb + (r >> 10))
                                 : ((r & (Bb - 1)) * Tt + (r >> 6));
            #pragma unroll
            for (int nt = 0; nt < 4; nt++) {
                int c = n0 + wn * 32 + nt * 8 + tig * 2;
                C[(size_t)ro * N + c]     = acc[mt][nt][rr * 2]     + bias[c];
                C[(size_t)ro * N + c + 1] = acc[mt][nt][rr * 2 + 1] + bias[c + 1];
            }
        }
    }
}

// ---------------- persistent recurrent kernel (dataflow, no global barrier) ----
// 128 blocks: bid&3 = batch group (16 batches), bid>>2 = hidden block hb (16 units).
// Each block produces chunk hb of h each step; publishes a monotonic flag.
// Warp w consumes chunks 4w..4w+3 (its k-slice), polling producer flags per chunk,
// double-buffered via cp.async so poll+load overlap the previous chunk's MMA.
#define PS 49

__global__ __launch_bounds__(256, 1) void gru_rec(
    const float* __restrict__ xg, const float* __restrict__ whh,
    const float* __restrict__ bhh, float* __restrict__ y)
{
    __shared__ __align__(16) float stage[8][2][16][20];  // [warp][buf][batch][k(16)+pad]
    __shared__ float part[8][16][PS];                    // [warp][batch][48 gate-rows]
    __shared__ float b_s[48];
    __shared__ unsigned s_base;

    const int bid  = blockIdx.x;
    const int grp  = bid & 3;
    const int hb   = bid >> 2;
    const int tid  = threadIdx.x;
    const int warp = tid >> 5, lane = tid & 31;
    const int gID  = lane >> 2, tig = lane & 3;
    const int bb   = tid >> 4, uu = tid & 15;
    const int bglob = grp * 16;
    const int k0w  = warp * 64;

    // one-time: W_hh fragments into registers (tf32-rounded)
    unsigned breg[8][6][2];
    #pragma unroll
    for (int nt = 0; nt < 6; nt++) {
        int r = nt * 8 + gID;                          // 0..47
        int grow = (r >> 4) * Hh + hb * 16 + (r & 15);
        const float* wrow = whh + (size_t)grow * Hh;
        #pragma unroll
        for (int ks = 0; ks < 8; ks++) {
            int k = k0w + ks * 8 + tig;
            breg[ks][nt][0] = __float_as_uint(to_tf32(wrow[k]));
            breg[ks][nt][1] = __float_as_uint(to_tf32(wrow[k + 4]));
        }
    }
    if (tid < 48) b_s[tid] = bhh[(tid >> 4) * Hh + hb * 16 + (tid & 15)];
    if (tid == 0) s_base = *(volatile unsigned*)&g_flag[grp][hb].v;  // equal across blocks
    __syncthreads();
    const unsigned base = s_base;

    const int b  = bglob + bb;
    const int ug = hb * 16 + uu;
    float hprev = 0.f;                                  // tf32-rounded h_{t-1}(b,ug)

    for (int t = 0; t < Tt; t++) {
        // prefetch input-side gates (consumed in gate phase)
        const size_t xb = ((size_t)t * Bb + b) * (size_t)G3;
        float xr = __ldg(xg + xb + ug);
        float xz = __ldg(xg + xb + Hh + ug);
        float xn = __ldg(xg + xb + 2 * Hh + ug);

        float acc[6][4];
        #pragma unroll
        for (int nt = 0; nt < 6; nt++) { acc[nt][0]=acc[nt][1]=acc[nt][2]=acc[nt][3]=0.f; }

        if (t > 0) {
            const float* ybase = y + ((size_t)(t - 1) * Bb + bglob) * Hh;
            const unsigned tgt = base + (unsigned)t;
            const int c0 = warp * 4;

            // prologue: chunk c0 -> buf 0
            {
                int j = c0;
                if (j != hb) waitflag(&g_flag[grp][j].v, tgt);
                #pragma unroll
                for (int i = 0; i < 2; i++) {
                    int idx = lane + 32 * i;
                    int row = idx >> 2, seg = idx & 3;
                    const float* src = ybase + (size_t)row * Hh + j * 16 + seg * 4;
                    asm volatile("cp.async.cg.shared.global [%0], [%1], 16;"
                                 :: "r"(smem_u32(&stage[warp][0][row][seg * 4])), "l"(src)
                                 : "memory");
                }
                asm volatile("cp.async.commit_group;" ::: "memory");
            }
            #pragma unroll
            for (int c = 0; c < 4; c++) {
                if (c < 3) {                            // prefetch next chunk
                    int j = c0 + c + 1;
                    if (j != hb) waitflag(&g_flag[grp][j].v, tgt);
                    #pragma unroll
                    for (int i = 0; i < 2; i++) {
                        int idx = lane + 32 * i;
                        int row = idx >> 2, seg = idx & 3;
                        const float* src = ybase + (size_t)row * Hh + j * 16 + seg * 4;
                        asm volatile("cp.async.cg.shared.global [%0], [%1], 16;"
                                     :: "r"(smem_u32(&stage[warp][(c + 1) & 1][row][seg * 4])), "l"(src)
                                     : "memory");
                    }
                    asm volatile("cp.async.commit_group;" ::: "memory");
                    asm volatile("cp.async.wait_group 1;" ::: "memory");
                } else {
                    asm volatile("cp.async.wait_group 0;" ::: "memory");
                }
                __syncwarp();
                const float (*st)[20] = stage[warp][c & 1];
                #pragma unroll
                for (int s = 0; s < 2; s++) {
                    const int kk = s * 8;
                    unsigned a[4];
                    a[0] = __float_as_uint(st[gID][kk + tig]);
                    a[1] = __float_as_uint(st[gID + 8][kk + tig]);
                    a[2] = __float_as_uint(st[gID][kk + tig + 4]);
                    a[3] = __float_as_uint(st[gID + 8][kk + tig + 4]);
                    #pragma unroll
                    for (int nt = 0; nt < 6; nt++)
                        mma_tf32(acc[nt], a, breg[c * 2 + s][nt][0], breg[c * 2 + s][nt][1]);
                }
            }
        }

        // partials to smem
        float* pw = &part[warp][0][0];
        #pragma unroll
        for (int nt = 0; nt < 6; nt++) {
            int c = nt * 8 + tig * 2;
            pw[gID * PS + c]           = acc[nt][0];
            pw[gID * PS + c + 1]       = acc[nt][1];
            pw[(gID + 8) * PS + c]     = acc[nt][2];
            pw[(gID + 8) * PS + c + 1] = acc[nt][3];
        }
        __syncthreads();

        // gate phase: fold 8-way k-reduction; one (batch, unit) per thread
        float hr = b_s[uu], hz = b_s[16 + uu], hn = b_s[32 + uu];
        #pragma unroll
        for (int w = 0; w < 8; w++) {
            const float* p = &part[w][bb][0];
            hr += p[uu]; hz += p[16 + uu]; hn += p[32 + uu];
        }
        float r = 1.f / (1.f + __expf(-(xr + hr)));
        float z = 1.f / (1.f + __expf(-(xz + hz)));
        float n = tanhf(xn + r * hn);
        float hnew = (1.f - z) * n + z * hprev;
        float hro = to_tf32(hnew);
        hprev = hro;
        y[((size_t)t * Bb + b) * Hh + ug] = hro;

        // publish: data fence, block sync (also protects `part` reuse), flag bump
        __threadfence();
        __syncthreads();
        if (tid == 0)
            *(volatile unsigned*)&g_flag[grp][hb].v = base + (unsigned)t + 1u;
    }
}

// ---------------- launch ----------------
extern "C" void kernel_launch(void* const* d_in, const int* in_sizes, int n_in,
                              void* d_out, int out_size)
{
    const float* x    = (const float*)d_in[0];
    const float* wih0 = (const float*)d_in[1];
    const float* whh0 = (const float*)d_in[2];
    const float* bih0 = (const float*)d_in[3];
    const float* bhh0 = (const float*)d_in[4];
    const float* wih1 = (const float*)d_in[5];
    const float* whh1 = (const float*)d_in[6];
    const float* bih1 = (const float*)d_in[7];
    const float* bhh1 = (const float*)d_in[8];
    const float* fcw  = (const float*)d_in[9];
    const float* fcb  = (const float*)d_in[10];
    float* out = (float*)d_out;

    float *xgp = 0, *yp = 0;
    cudaGetSymbolAddress((void**)&xgp, g_xg);
    cudaGetSymbolAddress((void**)&yp,  g_y);

    // xg0 (time-major out): rows of x are b*T+t -> write t*B+b   (mode 1)
    gemm_tf32<<<dim3(G3 / 64, MM / 128), 256>>>(x, wih0, bih0, xgp, MM, G3, Ii, 1);
    // layer 0 recurrence -> y (time-major)
    gru_rec<<<128, 256>>>(xgp, whh0, bhh0, yp);
    // xg1: y0 rows already t*B+b -> same order out                (mode 0)
    gemm_tf32<<<dim3(G3 / 64, MM / 128), 256>>>(yp, wih1, bih1, xgp, MM, G3, Hh, 0);
    // layer 1 recurrence -> y
    gru_rec<<<128, 256>>>(xgp, whh1, bhh1, yp);
    // FC: y1 rows t*B+b -> out rows b*T+t                         (mode 2)
    gemm_tf32<<<dim3(Ii / 64, MM / 128), 256>>>(yp, fcw, fcb, out, MM, Ii, Hh, 2);
}

// round 11
// speedup vs baseline: 1.6940x; 1.0788x over previous
#include <cuda_runtime.h>
#include <cstdint>

#define Bb 64
#define Tt 1024
#define Ii 64
#define Hh 512
#define G3 1536
#define MM (Bb*Tt)      // 65536 rows

// ---------------- scratch (device globals: allocation-free) ----------------
__device__ float g_xg[(size_t)MM * G3];   // input-side gates, TIME-MAJOR rows (t*B+b)
__device__ float g_y [(size_t)MM * Hh];   // hidden history, TIME-MAJOR rows (t*B+b)

struct __align__(128) PadFlag { unsigned v; unsigned pad[31]; };
__device__ PadFlag g_flag[4][32];         // per (group, producer-block) monotonic step flags

// ---------------- helpers ----------------
__device__ __forceinline__ float to_tf32(float x) {
    unsigned u;
    asm("cvt.rna.tf32.f32 %0, %1;" : "=r"(u) : "f"(x));
    return __uint_as_float(u);
}

__device__ __forceinline__ void mma_tf32(float* c, const unsigned* a, unsigned b0, unsigned b1) {
    asm("mma.sync.aligned.m16n8k8.row.col.f32.tf32.tf32.f32 "
        "{%0,%1,%2,%3},{%4,%5,%6,%7},{%8,%9},{%0,%1,%2,%3};"
        : "+f"(c[0]), "+f"(c[1]), "+f"(c[2]), "+f"(c[3])
        : "r"(a[0]), "r"(a[1]), "r"(a[2]), "r"(a[3]), "r"(b0), "r"(b1));
}

__device__ __forceinline__ unsigned smem_u32(const void* p) {
    return (unsigned)__cvta_generic_to_shared(p);
}

// hard spin — NO nanosleep (sleep quantum was the R8-R10 bottleneck)
__device__ __forceinline__ void waitflag(const unsigned* p, unsigned tgt) {
    unsigned v;
    do {
        asm volatile("ld.global.acquire.gpu.b32 %0, [%1];" : "=r"(v) : "l"(p) : "memory");
    } while ((int)(v - tgt) < 0);
}

// ---------------- generic tf32 GEMM: C[m][n] = sum_k A[m][k]*W[n][k] + bias[n] ----
// mode: output row remap. 0: ro=m  1: m=(b*T+t) -> ro=t*B+b   2: m=(t*B+b) -> ro=b*T+t
__global__ __launch_bounds__(256) void gemm_tf32(
    const float* __restrict__ A, const float* __restrict__ W,
    const float* __restrict__ bias, float* __restrict__ C,
    int M, int N, int K, int mode)
{
    __shared__ float As[128][20];
    __shared__ float Ws[64][20];
    const int tid  = threadIdx.x;
    const int warp = tid >> 5, lane = tid & 31;
    const int gID  = lane >> 2, tig = lane & 3;
    const int wm   = warp >> 1, wn = warp & 1;
    const int m0   = blockIdx.y * 128, n0 = blockIdx.x * 64;

    float acc[2][4][4];
    #pragma unroll
    for (int i = 0; i < 2; i++)
        #pragma unroll
        for (int j = 0; j < 4; j++)
            #pragma unroll
            for (int q = 0; q < 4; q++) acc[i][j][q] = 0.f;

    for (int k0 = 0; k0 < K; k0 += 16) {
        #pragma unroll
        for (int i = 0; i < 2; i++) {
            int idx = tid + i * 256;
            int r = idx >> 2, cb = idx & 3;
            float4 v = *(const float4*)(A + (size_t)(m0 + r) * K + k0 + cb * 4);
            *(float4*)(&As[r][cb * 4]) =
                make_float4(to_tf32(v.x), to_tf32(v.y), to_tf32(v.z), to_tf32(v.w));
        }
        {
            int r = tid >> 2, cb = tid & 3;
            float4 v = *(const float4*)(W + (size_t)(n0 + r) * K + k0 + cb * 4);
            *(float4*)(&Ws[r][cb * 4]) =
                make_float4(to_tf32(v.x), to_tf32(v.y), to_tf32(v.z), to_tf32(v.w));
        }
        __syncthreads();
        #pragma unroll
        for (int s = 0; s < 2; s++) {
            const int kk = s * 8;
            unsigned a[2][4];
            #pragma unroll
            for (int mt = 0; mt < 2; mt++) {
                int r = wm * 32 + mt * 16 + gID;
                a[mt][0] = __float_as_uint(As[r][kk + tig]);
                a[mt][1] = __float_as_uint(As[r + 8][kk + tig]);
                a[mt][2] = __float_as_uint(As[r][kk + tig + 4]);
                a[mt][3] = __float_as_uint(As[r + 8][kk + tig + 4]);
            }
            #pragma unroll
            for (int nt = 0; nt < 4; nt++) {
                int n = wn * 32 + nt * 8 + gID;
                unsigned b0 = __float_as_uint(Ws[n][kk + tig]);
                unsigned b1 = __float_as_uint(Ws[n][kk + tig + 4]);
                #pragma unroll
                for (int mt = 0; mt < 2; mt++)
                    mma_tf32(acc[mt][nt], a[mt], b0, b1);
            }
        }
        __syncthreads();
    }
    #pragma unroll
    for (int mt = 0; mt < 2; mt++) {
        #pragma unroll
        for (int rr = 0; rr < 2; rr++) {
            int r = m0 + wm * 32 + mt * 16 + rr * 8 + gID;
            int ro = (mode == 0) ? r
                   : (mode == 1) ? ((r & (Tt - 1)) * Bb + (r >> 10))
                                 : ((r & (Bb - 1)) * Tt + (r >> 6));
            #pragma unroll
            for (int nt = 0; nt < 4; nt++) {
                int c = n0 + wn * 32 + nt * 8 + tig * 2;
                C[(size_t)ro * N + c]     = acc[mt][nt][rr * 2]     + bias[c];
                C[(size_t)ro * N + c + 1] = acc[mt][nt][rr * 2 + 1] + bias[c + 1];
            }
        }
    }
}

// ---------------- persistent recurrent kernel (dataflow, hard-spin flags) ----
// 128 blocks: bid&3 = batch group (16 batches), bid>>2 = hidden block hb (16 units).
// Warp w consumes chunks 4w..4w+3 (its k-slice), double-buffered cp.async.
// The block's own chunk is read from smem (own[]), skipping global entirely.
#define PS 49

__global__ __launch_bounds__(256, 1) void gru_rec(
    const float* __restrict__ xg, const float* __restrict__ whh,
    const float* __restrict__ bhh, float* __restrict__ y)
{
    __shared__ __align__(16) float stage[8][2][16][20];  // [warp][buf][batch][k(16)+pad]
    __shared__ float own[16][20];                        // this block's h chunk (t-1)
    __shared__ float part[8][16][PS];                    // [warp][batch][48 gate-rows]
    __shared__ float b_s[48];
    __shared__ unsigned s_base;

    const int bid  = blockIdx.x;
    const int grp  = bid & 3;
    const int hb   = bid >> 2;
    const int tid  = threadIdx.x;
    const int warp = tid >> 5, lane = tid & 31;
    const int gID  = lane >> 2, tig = lane & 3;
    const int bb   = tid >> 4, uu = tid & 15;
    const int bglob = grp * 16;
    const int k0w  = warp * 64;

    // one-time: W_hh fragments into registers (tf32-rounded)
    unsigned breg[8][6][2];
    #pragma unroll
    for (int nt = 0; nt < 6; nt++) {
        int r = nt * 8 + gID;                          // 0..47
        int grow = (r >> 4) * Hh + hb * 16 + (r & 15);
        const float* wrow = whh + (size_t)grow * Hh;
        #pragma unroll
        for (int ks = 0; ks < 8; ks++) {
            int k = k0w + ks * 8 + tig;
            breg[ks][nt][0] = __float_as_uint(to_tf32(wrow[k]));
            breg[ks][nt][1] = __float_as_uint(to_tf32(wrow[k + 4]));
        }
    }
    if (tid < 48) b_s[tid] = bhh[(tid >> 4) * Hh + hb * 16 + (tid & 15)];
    if (tid == 0) s_base = *(volatile unsigned*)&g_flag[grp][hb].v;  // equal across blocks
    __syncthreads();
    const unsigned base = s_base;

    const int b  = bglob + bb;
    const int ug = hb * 16 + uu;
    float hprev = 0.f;                                  // tf32-rounded h_{t-1}(b,ug)

    for (int t = 0; t < Tt; t++) {
        // prefetch input-side gates (consumed in gate phase)
        const size_t xb = ((size_t)t * Bb + b) * (size_t)G3;
        float xr = __ldg(xg + xb + ug);
        float xz = __ldg(xg + xb + Hh + ug);
        float xn = __ldg(xg + xb + 2 * Hh + ug);

        float acc[6][4];
        #pragma unroll
        for (int nt = 0; nt < 6; nt++) { acc[nt][0]=acc[nt][1]=acc[nt][2]=acc[nt][3]=0.f; }

        if (t > 0) {
            const float* ybase = y + ((size_t)(t - 1) * Bb + bglob) * Hh;
            const unsigned tgt = base + (unsigned)t;
            const int c0 = warp * 4;

            // prologue: chunk c0 -> buf 0 (empty group if it's our own chunk)
            if (c0 != hb) {
                waitflag(&g_flag[grp][c0].v, tgt);
                #pragma unroll
                for (int i = 0; i < 2; i++) {
                    int idx = lane + 32 * i;
                    int row = idx >> 2, seg = idx & 3;
                    const float* src = ybase + (size_t)row * Hh + c0 * 16 + seg * 4;
                    asm volatile("cp.async.cg.shared.global [%0], [%1], 16;"
                                 :: "r"(smem_u32(&stage[warp][0][row][seg * 4])), "l"(src)
                                 : "memory");
                }
            }
            asm volatile("cp.async.commit_group;" ::: "memory");

            #pragma unroll
            for (int c = 0; c < 4; c++) {
                if (c < 3) {                            // prefetch next chunk
                    int j = c0 + c + 1;
                    if (j != hb) {
                        waitflag(&g_flag[grp][j].v, tgt);
                        #pragma unroll
                        for (int i = 0; i < 2; i++) {
                            int idx = lane + 32 * i;
                            int row = idx >> 2, seg = idx & 3;
                            const float* src = ybase + (size_t)row * Hh + j * 16 + seg * 4;
                            asm volatile("cp.async.cg.shared.global [%0], [%1], 16;"
                                         :: "r"(smem_u32(&stage[warp][(c + 1) & 1][row][seg * 4])), "l"(src)
                                         : "memory");
                        }
                    }
                    asm volatile("cp.async.commit_group;" ::: "memory");
                    asm volatile("cp.async.wait_group 1;" ::: "memory");
                } else {
                    asm volatile("cp.async.wait_group 0;" ::: "memory");
                }
                __syncwarp();
                const float (*st)[20] = (c0 + c == hb) ? own : stage[warp][c & 1];
                #pragma unroll
                for (int s = 0; s < 2; s++) {
                    const int kk = s * 8;
                    unsigned a[4];
                    a[0] = __float_as_uint(st[gID][kk + tig]);
                    a[1] = __float_as_uint(st[gID + 8][kk + tig]);
                    a[2] = __float_as_uint(st[gID][kk + tig + 4]);
                    a[3] = __float_as_uint(st[gID + 8][kk + tig + 4]);
                    #pragma unroll
                    for (int nt = 0; nt < 6; nt++)
                        mma_tf32(acc[nt], a, breg[c * 2 + s][nt][0], breg[c * 2 + s][nt][1]);
                }
            }
        }

        // partials to smem
        float* pw = &part[warp][0][0];
        #pragma unroll
        for (int nt = 0; nt < 6; nt++) {
            int c = nt * 8 + tig * 2;
            pw[gID * PS + c]           = acc[nt][0];
            pw[gID * PS + c + 1]       = acc[nt][1];
            pw[(gID + 8) * PS + c]     = acc[nt][2];
            pw[(gID + 8) * PS + c + 1] = acc[nt][3];
        }
        __syncthreads();

        // gate phase: fold 8-way k-reduction; one (batch, unit) per thread
        float hr = b_s[uu], hz = b_s[16 + uu], hn = b_s[32 + uu];
        #pragma unroll
        for (int w = 0; w < 8; w++) {
            const float* p = &part[w][bb][0];
            hr += p[uu]; hz += p[16 + uu]; hn += p[32 + uu];
        }
        float ar = xr + hr; ar = fminf(fmaxf(ar, -30.f), 30.f);
        float az = xz + hz; az = fminf(fmaxf(az, -30.f), 30.f);
        float r = __fdividef(1.f, 1.f + __expf(-ar));
        float z = __fdividef(1.f, 1.f + __expf(-az));
        float an = xn + r * hn; an = fminf(fmaxf(an, -15.f), 15.f);
        float n = 1.f - __fdividef(2.f, __expf(2.f * an) + 1.f);
        float hnew = (1.f - z) * n + z * hprev;
        float hro = to_tf32(hnew);
        hprev = hro;
        y[((size_t)t * Bb + b) * Hh + ug] = hro;
        own[bb][uu] = hro;                               // smem copy for own-chunk consumers

        // publish: block sync (orders all y stores + protects part/own), then
        // one release store (coop-groups grid-sync pattern; no per-thread fences)
        __syncthreads();
        if (tid == 0) {
            unsigned nv = base + (unsigned)t + 1u;
            asm volatile("st.global.release.gpu.b32 [%0], %1;"
                         :: "l"(&g_flag[grp][hb].v), "r"(nv) : "memory");
        }
    }
}

// ---------------- launch ----------------
extern "C" void kernel_launch(void* const* d_in, const int* in_sizes, int n_in,
                              void* d_out, int out_size)
{
    const float* x    = (const float*)d_in[0];
    const float* wih0 = (const float*)d_in[1];
    const float* whh0 = (const float*)d_in[2];
    const float* bih0 = (const float*)d_in[3];
    const float* bhh0 = (const float*)d_in[4];
    const float* wih1 = (const float*)d_in[5];
    const float* whh1 = (const float*)d_in[6];
    const float* bih1 = (const float*)d_in[7];
    const float* bhh1 = (const float*)d_in[8];
    const float* fcw  = (const float*)d_in[9];
    const float* fcb  = (const float*)d_in[10];
    float* out = (float*)d_out;

    float *xgp = 0, *yp = 0;
    cudaGetSymbolAddress((void**)&xgp, g_xg);
    cudaGetSymbolAddress((void**)&yp,  g_y);

    // xg0 (time-major out): rows of x are b*T+t -> write t*B+b   (mode 1)
    gemm_tf32<<<dim3(G3 / 64, MM / 128), 256>>>(x, wih0, bih0, xgp, MM, G3, Ii, 1);
    // layer 0 recurrence -> y (time-major)
    gru_rec<<<128, 256>>>(xgp, whh0, bhh0, yp);
    // xg1: y0 rows already t*B+b -> same order out                (mode 0)
    gemm_tf32<<<dim3(G3 / 64, MM / 128), 256>>>(yp, wih1, bih1, xgp, MM, G3, Hh, 0);
    // layer 1 recurrence -> y
    gru_rec<<<128, 256>>>(xgp, whh1, bhh1, yp);
    // FC: y1 rows t*B+b -> out rows b*T+t                         (mode 2)
    gemm_tf32<<<dim3(Ii / 64, MM / 128), 256>>>(yp, fcw, fcb, out, MM, Ii, Hh, 2);
}